// round 14
// baseline (speedup 1.0000x reference)
#include <cuda_runtime.h>
#include <cuda_fp16.h>
#include <cstdint>

#define S_LEN   2048
#define D_K     64
#define BH      64
#define MT      64
#define NT      64
#define PQ2     36    // half2 pad: Qh/Ph reads banks 4g+tig -> conflict-free
#define PKV2    72    // half2 pad: Kt/Vt reads banks 8tig+g -> conflict-free
#define THREADS 256
#define NTILES  (S_LEN / NT)          // 32
#define NBLOCKS (BH * (S_LEN / MT))   // 2048

__device__ float    g_linv[BH * S_LEN];
__device__ uint16_t g_mbits[(size_t)NBLOCKS * NTILES * THREADS];   // 33.5 MB

__device__ __forceinline__ uint32_t pack_h2(float lo, float hi) {
    half2 h = __floats2half2_rn(lo, hi);
    return *(uint32_t*)&h;
}

__device__ __forceinline__ void mma_f16(float c[4],
                                        uint32_t a0, uint32_t a1, uint32_t a2, uint32_t a3,
                                        uint32_t b0, uint32_t b1) {
    asm volatile(
        "mma.sync.aligned.m16n8k16.row.col.f32.f16.f16.f32 "
        "{%0,%1,%2,%3},{%4,%5,%6,%7},{%8,%9},{%0,%1,%2,%3};"
        : "+f"(c[0]), "+f"(c[1]), "+f"(c[2]), "+f"(c[3])
        : "r"(a0), "r"(a1), "r"(a2), "r"(a3), "r"(b0), "r"(b1));
}

// Q tile -> fp16 smem (scale 1/8 folded)
__device__ __forceinline__ void load_q(half2* Qh, const float* __restrict__ Qg, int tid) {
    const float4* q4 = (const float4*)Qg;
    #pragma unroll
    for (int i = 0; i < 4; i++) {
        int idx = i * THREADS + tid;
        float4 v = q4[idx];
        int row = idx >> 4;
        int c2  = (idx & 15) * 2;
        Qh[row * PQ2 + c2]     = __floats2half2_rn(v.x * 0.125f, v.y * 0.125f);
        Qh[row * PQ2 + c2 + 1] = __floats2half2_rn(v.z * 0.125f, v.w * 0.125f);
    }
}

// ===================== pass 1: row sums + mask compression =====================
__global__ __launch_bounds__(THREADS, 4)
void sdpa_stats(const float* __restrict__ Q, const float* __restrict__ K,
                const int* __restrict__ mask) {
    extern __shared__ char smraw[];
    half2* Qh  = (half2*)smraw;               // 64 x PQ2
    half2* Kt  = Qh + MT * PQ2;               // 32 x PKV2
    float* red = (float*)(Kt + 32 * PKV2);    // 64 x 4

    const int bh  = blockIdx.y;
    const int q0  = blockIdx.x * MT;
    const int myid = blockIdx.y * gridDim.x + blockIdx.x;
    const int tid = threadIdx.x;
    const int lane = tid & 31, wid = tid >> 5;
    const int g = lane >> 2, tig = lane & 3;
    const int wm = wid & 1, wn = wid >> 1;

    const float* Qg = Q + ((size_t)bh * S_LEN + q0) * D_K;
    const float* Kg = K + (size_t)bh * S_LEN * D_K;
    const int*   Mg = mask + (size_t)bh * S_LEN * S_LEN;
    uint16_t* mb_out = g_mbits + (size_t)myid * NTILES * THREADS + tid;

    load_q(Qh, Qg, tid);

    uint32_t kh2[8];
    #pragma unroll
    for (int i = 0; i < 4; i++) {
        int f = i * THREADS + tid;
        int key = f & 63, kb = f >> 6;
        float4 kv = *(const float4*)(Kg + (size_t)key * D_K + kb * 4);
        kh2[2 * i]     = pack_h2(kv.x, kv.y);
        kh2[2 * i + 1] = pack_h2(kv.z, kv.w);
    }

    float lp[2][2] = {};

    for (int kt = 0; kt < S_LEN; kt += NT) {
        __syncthreads();
        // K(t) STS
        #pragma unroll
        for (int i = 0; i < 4; i++) {
            int f = i * THREADS + tid;
            int key = f & 63, kb = f >> 6;
            *(uint32_t*)&Kt[(2 * kb)     * PKV2 + key] = kh2[2 * i];
            *(uint32_t*)&Kt[(2 * kb + 1) * PKV2 + key] = kh2[2 * i + 1];
        }

        // mask -> bitmask (overlaps QK)
        uint32_t mbits = 0;
        #pragma unroll
        for (int mb = 0; mb < 2; mb++) {
            int row = wm * 32 + mb * 16 + g;
            #pragma unroll
            for (int nf = 0; nf < 2; nf++) {
                int col = wn * 16 + nf * 8 + 2 * tig;
                int2 m0 = *(const int2*)(Mg + (size_t)(q0 + row)     * S_LEN + kt + col);
                int2 m1 = *(const int2*)(Mg + (size_t)(q0 + row + 8) * S_LEN + kt + col);
                int b = (mb * 2 + nf) * 4;
                mbits |= ((m0.x ? 1u : 0u) << b) | ((m0.y ? 2u : 0u) << b)
                       | ((m1.x ? 4u : 0u) << b) | ((m1.y ? 8u : 0u) << b);
            }
        }
        __syncthreads();

        // QK mma
        float acc[2][2][4] = {};
        #pragma unroll
        for (int j = 0; j < 4; j++) {
            uint32_t a[2][4];
            #pragma unroll
            for (int mb = 0; mb < 2; mb++) {
                int r = wm * 32 + mb * 16 + g;
                a[mb][0] = *(uint32_t*)&Qh[r       * PQ2 + 8 * j + tig];
                a[mb][1] = *(uint32_t*)&Qh[(r + 8) * PQ2 + 8 * j + tig];
                a[mb][2] = *(uint32_t*)&Qh[r       * PQ2 + 8 * j + tig + 4];
                a[mb][3] = *(uint32_t*)&Qh[(r + 8) * PQ2 + 8 * j + tig + 4];
            }
            #pragma unroll
            for (int nf = 0; nf < 2; nf++) {
                int nc = wn * 16 + nf * 8 + g;
                uint32_t b0 = *(uint32_t*)&Kt[(8 * j + tig)     * PKV2 + nc];
                uint32_t b1 = *(uint32_t*)&Kt[(8 * j + tig + 4) * PKV2 + nc];
                #pragma unroll
                for (int mb = 0; mb < 2; mb++)
                    mma_f16(acc[mb][nf], a[mb][0], a[mb][1], a[mb][2], a[mb][3], b0, b1);
            }
        }

        // K(t+1) prefetch
        {
            const float* Kn = Kg + (size_t)((kt + NT < S_LEN) ? kt + NT : 0) * D_K;
            #pragma unroll
            for (int i = 0; i < 4; i++) {
                int f = i * THREADS + tid;
                int key = f & 63, kb = f >> 6;
                float4 kv = *(const float4*)(Kn + (size_t)key * D_K + kb * 4);
                kh2[2 * i]     = pack_h2(kv.x, kv.y);
                kh2[2 * i + 1] = pack_h2(kv.z, kv.w);
            }
        }

        // exp + row sums; emit compressed mask
        #pragma unroll
        for (int mb = 0; mb < 2; mb++)
            #pragma unroll
            for (int nf = 0; nf < 2; nf++) {
                int b = (mb * 2 + nf) * 4;
                lp[mb][0] += ((mbits >> b & 1u) ? __expf(acc[mb][nf][0]) : 0.f)
                           + ((mbits >> b & 2u) ? __expf(acc[mb][nf][1]) : 0.f);
                lp[mb][1] += ((mbits >> b & 4u) ? __expf(acc[mb][nf][2]) : 0.f)
                           + ((mbits >> b & 8u) ? __expf(acc[mb][nf][3]) : 0.f);
            }
        mb_out[(kt >> 6) * THREADS] = (uint16_t)mbits;
    }

    // reduce -> g_linv
    #pragma unroll
    for (int mb = 0; mb < 2; mb++)
        #pragma unroll
        for (int h = 0; h < 2; h++) {
            float s = lp[mb][h];
            s += __shfl_xor_sync(0xffffffffu, s, 1);
            s += __shfl_xor_sync(0xffffffffu, s, 2);
            lp[mb][h] = s;
        }
    if (tig == 0)
        #pragma unroll
        for (int mb = 0; mb < 2; mb++)
            #pragma unroll
            for (int h = 0; h < 2; h++)
                red[(wm * 32 + mb * 16 + g + h * 8) * 4 + wn] = lp[mb][h];
    __syncthreads();
    if (tid < MT)
        g_linv[(size_t)bh * S_LEN + q0 + tid] =
            1.f / (red[tid * 4] + red[tid * 4 + 1] + red[tid * 4 + 2] + red[tid * 4 + 3]);
}

// ============== pass 2: recompute, write normalized attn once, PV ==============
__global__ __launch_bounds__(THREADS, 3)
void sdpa_emit(const float* __restrict__ Q, const float* __restrict__ K,
               const float* __restrict__ V, float* __restrict__ out) {
    extern __shared__ char smraw[];
    half2* Qh = (half2*)smraw;               // 64 x PQ2
    half2* Ph = Qh + MT * PQ2;               // 64 x PQ2
    half2* Kt = Ph + MT * PQ2;               // 32 x PKV2
    half2* Vt = Kt + 32 * PKV2;              // 32 x PKV2

    const int bh  = blockIdx.y;
    const int q0  = blockIdx.x * MT;
    const int myid = blockIdx.y * gridDim.x + blockIdx.x;
    const int tid = threadIdx.x;
    const int lane = tid & 31, wid = tid >> 5;
    const int g = lane >> 2, tig = lane & 3;
    const int wm = wid & 1, wn = wid >> 1;

    const float* Qg = Q + ((size_t)bh * S_LEN + q0) * D_K;
    const float* Kg = K + (size_t)bh * S_LEN * D_K;
    const float* Vg = V + (size_t)bh * S_LEN * D_K;
    float* ctx  = out + (size_t)bh * S_LEN * D_K;
    float* attn = out + (size_t)BH * S_LEN * D_K + (size_t)bh * S_LEN * S_LEN;
    const uint16_t* mb_in = g_mbits + (size_t)myid * NTILES * THREADS + tid;

    // l_inv for owned rows
    const float* lig = g_linv + (size_t)bh * S_LEN + q0;
    float li[2][2];
    #pragma unroll
    for (int mb = 0; mb < 2; mb++) {
        int row = wm * 32 + mb * 16 + g;
        li[mb][0] = lig[row];
        li[mb][1] = lig[row + 8];
    }

    load_q(Qh, Qg, tid);

    uint32_t kh2[8];
    #pragma unroll
    for (int i = 0; i < 4; i++) {
        int f = i * THREADS + tid;
        int key = f & 63, kb = f >> 6;
        float4 kv = *(const float4*)(Kg + (size_t)key * D_K + kb * 4);
        kh2[2 * i]     = pack_h2(kv.x, kv.y);
        kh2[2 * i + 1] = pack_h2(kv.z, kv.w);
    }

    float o[2][2][4] = {};

    for (int kt = 0; kt < S_LEN; kt += NT) {
        __syncthreads();

        // K(t) STS
        #pragma unroll
        for (int i = 0; i < 4; i++) {
            int f = i * THREADS + tid;
            int key = f & 63, kb = f >> 6;
            *(uint32_t*)&Kt[(2 * kb)     * PKV2 + key] = kh2[2 * i];
            *(uint32_t*)&Kt[(2 * kb + 1) * PKV2 + key] = kh2[2 * i + 1];
        }

        // V(t) LDG (register-held, long cover — R10 scheme)
        float4 va[2], vb[2];
        {
            int dq = tid & 15;
            #pragma unroll
            for (int i2 = 0; i2 < 2; i2++) {
                int k2 = (tid >> 4) + 16 * i2;
                va[i2] = *(const float4*)(Vg + (size_t)(kt + 2 * k2)     * D_K + 4 * dq);
                vb[i2] = *(const float4*)(Vg + (size_t)(kt + 2 * k2 + 1) * D_K + 4 * dq);
            }
        }

        // compressed mask: ONE ldg.u16 per thread per tile
        uint32_t mbits = mb_in[(kt >> 6) * THREADS];
        __syncthreads();

        // QK mma
        float acc[2][2][4] = {};
        #pragma unroll
        for (int j = 0; j < 4; j++) {
            uint32_t a[2][4];
            #pragma unroll
            for (int mb = 0; mb < 2; mb++) {
                int r = wm * 32 + mb * 16 + g;
                a[mb][0] = *(uint32_t*)&Qh[r       * PQ2 + 8 * j + tig];
                a[mb][1] = *(uint32_t*)&Qh[(r + 8) * PQ2 + 8 * j + tig];
                a[mb][2] = *(uint32_t*)&Qh[r       * PQ2 + 8 * j + tig + 4];
                a[mb][3] = *(uint32_t*)&Qh[(r + 8) * PQ2 + 8 * j + tig + 4];
            }
            #pragma unroll
            for (int nf = 0; nf < 2; nf++) {
                int nc = wn * 16 + nf * 8 + g;
                uint32_t b0 = *(uint32_t*)&Kt[(8 * j + tig)     * PKV2 + nc];
                uint32_t b1 = *(uint32_t*)&Kt[(8 * j + tig + 4) * PKV2 + nc];
                #pragma unroll
                for (int mb = 0; mb < 2; mb++)
                    mma_f16(acc[mb][nf], a[mb][0], a[mb][1], a[mb][2], a[mb][3], b0, b1);
            }
        }

        // p = mask*exp(s)*l_inv: normalized attn store (once), Ph store
        #pragma unroll
        for (int mb = 0; mb < 2; mb++) {
            int row = wm * 32 + mb * 16 + g;
            #pragma unroll
            for (int nf = 0; nf < 2; nf++) {
                int col = wn * 16 + nf * 8 + 2 * tig;
                int b = (mb * 2 + nf) * 4;
                float p00 = (mbits >> b & 1u) ? __expf(acc[mb][nf][0]) * li[mb][0] : 0.f;
                float p01 = (mbits >> b & 2u) ? __expf(acc[mb][nf][1]) * li[mb][0] : 0.f;
                float p10 = (mbits >> b & 4u) ? __expf(acc[mb][nf][2]) * li[mb][1] : 0.f;
                float p11 = (mbits >> b & 8u) ? __expf(acc[mb][nf][3]) * li[mb][1] : 0.f;
                *(float2*)(attn + (size_t)(q0 + row)     * S_LEN + kt + col) = make_float2(p00, p01);
                *(float2*)(attn + (size_t)(q0 + row + 8) * S_LEN + kt + col) = make_float2(p10, p11);
                int k2i = wn * 8 + 4 * nf + tig;
                *(uint32_t*)&Ph[row       * PQ2 + k2i] = pack_h2(p00, p01);
                *(uint32_t*)&Ph[(row + 8) * PQ2 + k2i] = pack_h2(p10, p11);
            }
        }

        // V(t) STS
        {
            int dq = tid & 15;
            #pragma unroll
            for (int i2 = 0; i2 < 2; i2++) {
                int k2 = (tid >> 4) + 16 * i2;
                uint4 h;
                h.x = pack_h2(va[i2].x, vb[i2].x);
                h.y = pack_h2(va[i2].y, vb[i2].y);
                h.z = pack_h2(va[i2].z, vb[i2].z);
                h.w = pack_h2(va[i2].w, vb[i2].w);
                *(uint4*)&Vt[k2 * PKV2 + 4 * dq] = h;
            }
        }

        // K(t+1) prefetch
        {
            const float* Kn = Kg + (size_t)((kt + NT < S_LEN) ? kt + NT : 0) * D_K;
            #pragma unroll
            for (int i = 0; i < 4; i++) {
                int f = i * THREADS + tid;
                int key = f & 63, kb = f >> 6;
                float4 kv = *(const float4*)(Kn + (size_t)key * D_K + kb * 4);
                kh2[2 * i]     = pack_h2(kv.x, kv.y);
                kh2[2 * i + 1] = pack_h2(kv.z, kv.w);
            }
        }
        __syncthreads();

        // O += P V
        #pragma unroll
        for (int j = 0; j < 4; j++) {
            uint32_t a[2][4];
            #pragma unroll
            for (int mb = 0; mb < 2; mb++) {
                int r = wm * 32 + mb * 16 + g;
                a[mb][0] = *(uint32_t*)&Ph[r       * PQ2 + 8 * j + tig];
                a[mb][1] = *(uint32_t*)&Ph[(r + 8) * PQ2 + 8 * j + tig];
                a[mb][2] = *(uint32_t*)&Ph[r       * PQ2 + 8 * j + tig + 4];
                a[mb][3] = *(uint32_t*)&Ph[(r + 8) * PQ2 + 8 * j + tig + 4];
            }
            #pragma unroll
            for (int nf = 0; nf < 2; nf++) {
                int dc = wn * 16 + nf * 8 + g;
                uint32_t b0 = *(uint32_t*)&Vt[(8 * j + tig)     * PKV2 + dc];
                uint32_t b1 = *(uint32_t*)&Vt[(8 * j + tig + 4) * PKV2 + dc];
                #pragma unroll
                for (int mb = 0; mb < 2; mb++)
                    mma_f16(o[mb][nf], a[mb][0], a[mb][1], a[mb][2], a[mb][3], b0, b1);
            }
        }
    }

    // context (already normalized)
    #pragma unroll
    for (int mb = 0; mb < 2; mb++) {
        int row = wm * 32 + mb * 16 + g;
        #pragma unroll
        for (int nf = 0; nf < 2; nf++) {
            int col = wn * 16 + nf * 8 + 2 * tig;
            *(float2*)(ctx + (size_t)(q0 + row)     * D_K + col) =
                make_float2(o[mb][nf][0], o[mb][nf][1]);
            *(float2*)(ctx + (size_t)(q0 + row + 8) * D_K + col) =
                make_float2(o[mb][nf][2], o[mb][nf][3]);
        }
    }
}

extern "C" void kernel_launch(void* const* d_in, const int* in_sizes, int n_in,
                              void* d_out, int out_size) {
    const float* Q    = (const float*)d_in[0];
    const float* K    = (const float*)d_in[1];
    const float* V    = (const float*)d_in[2];
    const int*   mask = (const int*)d_in[3];
    float* out = (float*)d_out;

    const int smem1 = (MT * PQ2 + 32 * PKV2) * 4 + MT * 4 * sizeof(float);    // ~19 KB
    const int smem2 = (2 * MT * PQ2 + 2 * 32 * PKV2) * 4;                      // ~37 KB
    cudaFuncSetAttribute(sdpa_stats, cudaFuncAttributeMaxDynamicSharedMemorySize, smem1);
    cudaFuncSetAttribute(sdpa_emit,  cudaFuncAttributeMaxDynamicSharedMemorySize, smem2);

    dim3 grid(S_LEN / MT, BH);   // (32, 64)
    sdpa_stats<<<grid, THREADS, smem1>>>(Q, K, mask);
    sdpa_emit <<<grid, THREADS, smem2>>>(Q, K, V, out);
}